// round 1
// baseline (speedup 1.0000x reference)
#include <cuda_runtime.h>
#include <stdint.h>

#define HH 128
#define WW 160
#define HWSZ (HH * WW)          // 20480
#define BMAX 4
#define FLOW_SCALE 160.0f

// Dedup bitmap: one bit per (b, pol, src, fw). 4*2*20480*20480 bits = 400 MiB.
#define BITMAP_WORDS ((size_t)BMAX * 2 * HWSZ * HWSZ / 32)   // 104,857,600 u32
__device__ uint32_t g_bitmap[BITMAP_WORDS];
__device__ int      g_contrib[BMAX * 2 * HWSZ];

// ---------------------------------------------------------------------------
// Zero the bitmap (vectorized), plus contrib and d_out in the same sweep.
// ---------------------------------------------------------------------------
__global__ void zero_kernel(float* __restrict__ out, int out_n) {
    size_t tid    = (size_t)blockIdx.x * blockDim.x + threadIdx.x;
    size_t nthr   = (size_t)gridDim.x * blockDim.x;
    // bitmap as uint4
    uint4* bm = reinterpret_cast<uint4*>(g_bitmap);
    size_t n4 = BITMAP_WORDS / 4;
    uint4 z4 = make_uint4(0u, 0u, 0u, 0u);
    for (size_t i = tid; i < n4; i += nthr) bm[i] = z4;
    // contrib + out (small)
    for (size_t i = tid; i < (size_t)BMAX * 2 * HWSZ; i += nthr) g_contrib[i] = 0;
    for (size_t i = tid; i < (size_t)out_n; i += nthr) out[i] = 0.0f;
}

// ---------------------------------------------------------------------------
// Per-event: gather flow, warp, round(half-even), scatter iwe + dedup contrib.
// ---------------------------------------------------------------------------
__global__ void event_kernel(const float* __restrict__ flow,
                             const float4* __restrict__ events,
                             float* __restrict__ out,
                             int N, int total) {
    int i = blockIdx.x * blockDim.x + threadIdx.x;
    if (i >= total) return;

    int b = i / N;

    float4 e = events[i];           // (t, y, x, p), coalesced float4 load
    float t = e.x, y = e.y, x = e.z, p = e.w;

    // src = y*W + x  (y,x are exact small integers in float)
    int src = (int)(__fadd_rn(__fmul_rn(y, (float)WW), x));

    const float* fb = flow + (size_t)b * 2 * HWSZ;
    float fx = __ldg(fb + src);          // flow[b,0,src]
    float fy = __ldg(fb + HWSZ + src);   // flow[b,1,src]

    // warped = yx + (1-t) * flow * 160   (exact ref op order, no FMA)
    float s  = __fadd_rn(1.0f, -t);
    float wy = __fadd_rn(y, __fmul_rn(__fmul_rn(s, fy), FLOW_SCALE));
    float wx = __fadd_rn(x, __fmul_rn(__fmul_rn(s, fx), FLOW_SCALE));

    // jnp.round == round half to even == rintf (default rounding mode)
    float ry = rintf(wy);
    float rx = rintf(wx);

    // valid check on the rounded floats, as in the reference
    if (!(ry >= 0.0f && ry < (float)HH && rx >= 0.0f && rx < (float)WW))
        return;  // weight 0 -> contributes nothing to iwe or contrib

    int fw = (int)ry * WW + (int)rx;
    int c  = (p > 0.0f) ? 0 : 1;     // channel 0 = pos (p>0), 1 = neg

    size_t chan = (size_t)b * 2 + c;

    // iwe scatter-add (all weights are 1.0f -> exact, order independent)
    atomicAdd(out + chan * HWSZ + fw, 1.0f);

    // dedup on (b, pol, src, fw)
    size_t bit  = (chan * HWSZ + (size_t)src) * HWSZ + (size_t)fw;
    uint32_t m  = 1u << ((uint32_t)bit & 31u);
    uint32_t old = atomicOr(&g_bitmap[bit >> 5], m);
    if ((old & m) == 0u)
        atomicAdd(&g_contrib[chan * HWSZ + fw], 1);
}

// ---------------------------------------------------------------------------
// Final divide: out = contrib>0 ? out/contrib : out
// ---------------------------------------------------------------------------
__global__ void div_kernel(float* __restrict__ out, int n) {
    int i = blockIdx.x * blockDim.x + threadIdx.x;
    if (i >= n) return;
    int c = g_contrib[i];
    if (c > 0) out[i] = out[i] / (float)c;
}

extern "C" void kernel_launch(void* const* d_in, const int* in_sizes, int n_in,
                              void* d_out, int out_size) {
    const float*  flow   = (const float*)d_in[0];   // (B, 2, H, W)
    const float4* events = (const float4*)d_in[1];  // (B, N, 4)
    float* out = (float*)d_out;                     // (B, 2, H, W)

    int B = in_sizes[0] / (2 * HWSZ);
    if (B > BMAX) B = BMAX;
    int N = in_sizes[1] / (4 * B);
    int total = B * N;

    // 1) zero bitmap + contrib + out
    zero_kernel<<<8192, 256>>>(out, out_size);

    // 2) per-event accumulation + dedup
    int threads = 256;
    int blocks  = (total + threads - 1) / threads;
    event_kernel<<<blocks, threads>>>(flow, events, out, N, total);

    // 3) normalize by distinct-source counts
    int dn = B * 2 * HWSZ;
    div_kernel<<<(dn + 255) / 256, 256>>>(out, dn);
}

// round 2
// speedup vs baseline: 1.8463x; 1.8463x over previous
#include <cuda_runtime.h>
#include <stdint.h>

#define HH 128
#define WW 160
#define HWSZ (HH * WW)          // 20480
#define BMAX 4
#define FLOW_SCALE 160.0f

// Per-batch open-addressing hash table for distinct (pol, src, fw) keys.
// Key = (pol<<30)|(src<<15)|fw  (31 bits). Slot stores key+1; 0 = empty.
// 2M slots x 4B x 4 batches = 32 MB (L2-resident on GB300).
#define TBITS 21
#define TSIZE (1u << TBITS)
#define TMASK (TSIZE - 1u)
__device__ uint32_t g_hash[(size_t)BMAX * TSIZE];
__device__ int      g_contrib[BMAX * 2 * HWSZ];

// ---------------------------------------------------------------------------
// Zero hash tables + contrib + d_out.
// ---------------------------------------------------------------------------
__global__ void zero_kernel(float* __restrict__ out, int out_n) {
    size_t tid  = (size_t)blockIdx.x * blockDim.x + threadIdx.x;
    size_t nthr = (size_t)gridDim.x * blockDim.x;
    uint4* hm = reinterpret_cast<uint4*>(g_hash);
    size_t n4 = ((size_t)BMAX * TSIZE) / 4;
    uint4 z4 = make_uint4(0u, 0u, 0u, 0u);
    for (size_t i = tid; i < n4; i += nthr) hm[i] = z4;
    for (size_t i = tid; i < (size_t)BMAX * 2 * HWSZ; i += nthr) g_contrib[i] = 0;
    for (size_t i = tid; i < (size_t)out_n; i += nthr) out[i] = 0.0f;
}

// ---------------------------------------------------------------------------
// Per-event: gather flow, warp, round(half-even), scatter iwe + hash dedup.
// ---------------------------------------------------------------------------
__global__ void event_kernel(const float* __restrict__ flow,
                             const float4* __restrict__ events,
                             float* __restrict__ out,
                             int N, int total) {
    int i = blockIdx.x * blockDim.x + threadIdx.x;
    if (i >= total) return;

    int b = i / N;

    float4 e = events[i];           // (t, y, x, p)
    float t = e.x, y = e.y, x = e.z, p = e.w;

    int src = (int)(__fadd_rn(__fmul_rn(y, (float)WW), x));

    const float* fb = flow + (size_t)b * 2 * HWSZ;
    float fx = __ldg(fb + src);          // flow[b,0,src]
    float fy = __ldg(fb + HWSZ + src);   // flow[b,1,src]

    // warped = yx + (1-t) * flow * 160   (exact ref op order, no FMA)
    float s  = __fadd_rn(1.0f, -t);
    float wy = __fadd_rn(y, __fmul_rn(__fmul_rn(s, fy), FLOW_SCALE));
    float wx = __fadd_rn(x, __fmul_rn(__fmul_rn(s, fx), FLOW_SCALE));

    // jnp.round == round half to even == rintf
    float ry = rintf(wy);
    float rx = rintf(wx);

    if (!(ry >= 0.0f && ry < (float)HH && rx >= 0.0f && rx < (float)WW))
        return;

    int fw = (int)ry * WW + (int)rx;
    int c  = (p > 0.0f) ? 0 : 1;     // 0 = pos channel, 1 = neg channel

    size_t chan = (size_t)b * 2 + c;

    // iwe scatter-add (all weights 1.0f -> exact)
    atomicAdd(out + chan * HWSZ + fw, 1.0f);

    // hash dedup on (pol, src, fw) within batch b
    uint32_t key = ((uint32_t)c << 30) | ((uint32_t)src << 15) | (uint32_t)fw;
    uint32_t tag = key + 1u;
    uint32_t h   = (key * 2654435761u) >> (32 - TBITS);
    uint32_t* tbl = g_hash + ((size_t)b << TBITS);

    while (true) {
        uint32_t cur = tbl[h];         // fast-path read (slots go 0->tag once)
        if (cur == tag) break;         // duplicate
        if (cur == 0u) {
            uint32_t old = atomicCAS(&tbl[h], 0u, tag);
            if (old == 0u) {           // first occurrence of this key
                atomicAdd(&g_contrib[chan * HWSZ + fw], 1);
                break;
            }
            if (old == tag) break;     // lost race to same key
        }
        h = (h + 1u) & TMASK;          // probe next
    }
}

// ---------------------------------------------------------------------------
// Final divide: out = contrib>0 ? out/contrib : out
// ---------------------------------------------------------------------------
__global__ void div_kernel(float* __restrict__ out, int n) {
    int i = blockIdx.x * blockDim.x + threadIdx.x;
    if (i >= n) return;
    int c = g_contrib[i];
    if (c > 0) out[i] = out[i] / (float)c;
}

extern "C" void kernel_launch(void* const* d_in, const int* in_sizes, int n_in,
                              void* d_out, int out_size) {
    const float*  flow   = (const float*)d_in[0];   // (B, 2, H, W)
    const float4* events = (const float4*)d_in[1];  // (B, N, 4)
    float* out = (float*)d_out;                     // (B, 2, H, W)

    int B = in_sizes[0] / (2 * HWSZ);
    if (B > BMAX) B = BMAX;
    int N = in_sizes[1] / (4 * B);
    int total = B * N;

    zero_kernel<<<4096, 256>>>(out, out_size);

    int threads = 256;
    int blocks  = (total + threads - 1) / threads;
    event_kernel<<<blocks, threads>>>(flow, events, out, N, total);

    int dn = B * 2 * HWSZ;
    div_kernel<<<(dn + 255) / 256, 256>>>(out, dn);
}

// round 3
// speedup vs baseline: 2.2496x; 1.2184x over previous
#include <cuda_runtime.h>
#include <stdint.h>

#define HH 128
#define WW 160
#define HWSZ (HH * WW)          // 20480
#define BMAX 4
#define FLOW_SCALE 160.0f

// Per-batch open-addressing hash table for distinct (pol, src, fw) keys.
// Key = (pol<<30)|(src<<15)|fw (31 bits). Slot stores key+1; 0 = empty.
#define TBITS 21
#define TSIZE (1u << TBITS)
#define TMASK (TSIZE - 1u)
__device__ uint32_t g_hash[(size_t)BMAX * TSIZE];   // 32 MB, L2-resident
__device__ int      g_contrib[BMAX * 2 * HWSZ];
__device__ float2   g_flow2[BMAX * HWSZ];           // interleaved (fx, fy)

// ---------------------------------------------------------------------------
// Zero hash/contrib/out AND build the interleaved flow, one sweep.
// ---------------------------------------------------------------------------
__global__ void prep_kernel(const float* __restrict__ flow,
                            float* __restrict__ out, int out_n, int B) {
    size_t tid  = (size_t)blockIdx.x * blockDim.x + threadIdx.x;
    size_t nthr = (size_t)gridDim.x * blockDim.x;

    uint4* hm = reinterpret_cast<uint4*>(g_hash);
    size_t n4 = ((size_t)BMAX * TSIZE) / 4;
    uint4 z4 = make_uint4(0u, 0u, 0u, 0u);
    for (size_t i = tid; i < n4; i += nthr) hm[i] = z4;

    for (size_t i = tid; i < (size_t)BMAX * 2 * HWSZ; i += nthr) g_contrib[i] = 0;
    for (size_t i = tid; i < (size_t)out_n; i += nthr) out[i] = 0.0f;

    size_t nflow = (size_t)B * HWSZ;
    for (size_t i = tid; i < nflow; i += nthr) {
        size_t b = i / HWSZ, j = i % HWSZ;
        const float* fb = flow + b * 2 * HWSZ;
        g_flow2[i] = make_float2(fb[j], fb[HWSZ + j]);  // (fx, fy)
    }
}

// ---------------------------------------------------------------------------
// Per-event: gather flow2, warp, round(half-even), scatter iwe + hash dedup.
// ---------------------------------------------------------------------------
__global__ void event_kernel(const float4* __restrict__ events,
                             float* __restrict__ out,
                             int N, int total) {
    int base = (blockIdx.x * blockDim.x + threadIdx.x) * 2;

#pragma unroll
    for (int k = 0; k < 2; k++) {
        int i = base + k;
        if (i >= total) return;

        int b = i / N;

        float4 e = events[i];           // (t, y, x, p)
        float t = e.x, y = e.y, x = e.z, p = e.w;

        int src = (int)(__fadd_rn(__fmul_rn(y, (float)WW), x));

        float2 f = __ldg(&g_flow2[(size_t)b * HWSZ + src]);  // (fx, fy)

        // warped = yx + (1-t) * flow * 160   (exact ref op order, no FMA)
        float s  = __fadd_rn(1.0f, -t);
        float wy = __fadd_rn(y, __fmul_rn(__fmul_rn(s, f.y), FLOW_SCALE));
        float wx = __fadd_rn(x, __fmul_rn(__fmul_rn(s, f.x), FLOW_SCALE));

        // jnp.round == round half to even == rintf
        float ry = rintf(wy);
        float rx = rintf(wx);

        if (!(ry >= 0.0f && ry < (float)HH && rx >= 0.0f && rx < (float)WW))
            continue;

        int fw = (int)ry * WW + (int)rx;
        int c  = (p > 0.0f) ? 0 : 1;

        size_t chan = (size_t)b * 2 + c;

        atomicAdd(out + chan * HWSZ + fw, 1.0f);

        // hash dedup: direct CAS (slots go 0 -> tag exactly once)
        uint32_t key = ((uint32_t)c << 30) | ((uint32_t)src << 15) | (uint32_t)fw;
        uint32_t tag = key + 1u;
        uint32_t h   = (key * 2654435761u) >> (32 - TBITS);
        uint32_t* tbl = g_hash + ((size_t)b << TBITS);

        while (true) {
            uint32_t old = atomicCAS(&tbl[h], 0u, tag);
            if (old == 0u) {                       // first occurrence
                atomicAdd(&g_contrib[chan * HWSZ + fw], 1);
                break;
            }
            if (old == tag) break;                 // duplicate
            h = (h + 1u) & TMASK;                  // collision: probe next
        }
    }
}

// ---------------------------------------------------------------------------
// Final divide: out = contrib>0 ? out/contrib : out
// ---------------------------------------------------------------------------
__global__ void div_kernel(float* __restrict__ out, int n) {
    int i = blockIdx.x * blockDim.x + threadIdx.x;
    if (i >= n) return;
    int c = g_contrib[i];
    if (c > 0) out[i] = out[i] / (float)c;
}

extern "C" void kernel_launch(void* const* d_in, const int* in_sizes, int n_in,
                              void* d_out, int out_size) {
    const float*  flow   = (const float*)d_in[0];   // (B, 2, H, W)
    const float4* events = (const float4*)d_in[1];  // (B, N, 4)
    float* out = (float*)d_out;                     // (B, 2, H, W)

    int B = in_sizes[0] / (2 * HWSZ);
    if (B > BMAX) B = BMAX;
    int N = in_sizes[1] / (4 * B);
    int total = B * N;

    prep_kernel<<<4096, 256>>>(flow, out, out_size, B);

    int threads = 256;
    int nthreads = (total + 1) / 2;
    int blocks   = (nthreads + threads - 1) / threads;
    event_kernel<<<blocks, threads>>>(events, out, N, total);

    int dn = B * 2 * HWSZ;
    div_kernel<<<(dn + 255) / 256, 256>>>(out, dn);
}

// round 4
// speedup vs baseline: 2.3246x; 1.0334x over previous
#include <cuda_runtime.h>
#include <stdint.h>

#define HH 128
#define WW 160
#define HWSZ (HH * WW)          // 20480
#define BMAX 4
#define FLOW_SCALE 160.0f

// Per-batch open-addressing hash table for distinct (pol, src, fw) keys.
// Key = (pol<<30)|(src<<15)|fw (31 bits). Slot stores key+1; 0 = empty.
#define TBITS 20
#define TSIZE (1u << TBITS)
#define TMASK (TSIZE - 1u)
__device__ uint32_t g_hash[(size_t)BMAX * TSIZE];         // 16 MB, L2-resident
// Packed accumulator: low 32 = event count, high 32 = distinct-src count.
__device__ unsigned long long g_acc[BMAX * 2 * HWSZ];     // 1.25 MB
__device__ float2   g_flow2[BMAX * HWSZ];                 // interleaved (fx, fy)

// ---------------------------------------------------------------------------
// Zero hash + acc AND build the interleaved flow, one sweep.
// ---------------------------------------------------------------------------
__global__ void prep_kernel(const float* __restrict__ flow, int B) {
    size_t tid  = (size_t)blockIdx.x * blockDim.x + threadIdx.x;
    size_t nthr = (size_t)gridDim.x * blockDim.x;

    uint4* hm = reinterpret_cast<uint4*>(g_hash);
    size_t n4 = ((size_t)BMAX * TSIZE) / 4;
    uint4 z4 = make_uint4(0u, 0u, 0u, 0u);
    for (size_t i = tid; i < n4; i += nthr) hm[i] = z4;

    ulonglong2* am = reinterpret_cast<ulonglong2*>(g_acc);
    size_t na = ((size_t)BMAX * 2 * HWSZ) / 2;
    for (size_t i = tid; i < na; i += nthr) am[i] = make_ulonglong2(0ull, 0ull);

    size_t nflow = (size_t)B * HWSZ;
    for (size_t i = tid; i < nflow; i += nthr) {
        size_t b = i / HWSZ, j = i % HWSZ;
        const float* fb = flow + b * 2 * HWSZ;
        g_flow2[i] = make_float2(fb[j], fb[HWSZ + j]);  // (fx, fy)
    }
}

// ---------------------------------------------------------------------------
// Per-event: gather flow2, warp, round(half-even), hash dedup, fused u64 add.
// ---------------------------------------------------------------------------
__global__ void event_kernel(const float4* __restrict__ events,
                             int N, int total) {
    int base = (blockIdx.x * blockDim.x + threadIdx.x) * 2;

#pragma unroll
    for (int k = 0; k < 2; k++) {
        int i = base + k;
        if (i >= total) return;

        int b = i / N;

        float4 e = events[i];           // (t, y, x, p)
        float t = e.x, y = e.y, x = e.z, p = e.w;

        int src = (int)(__fadd_rn(__fmul_rn(y, (float)WW), x));

        float2 f = __ldg(&g_flow2[(size_t)b * HWSZ + src]);  // (fx, fy)

        // warped = yx + (1-t) * flow * 160   (exact ref op order, no FMA)
        float s  = __fadd_rn(1.0f, -t);
        float wy = __fadd_rn(y, __fmul_rn(__fmul_rn(s, f.y), FLOW_SCALE));
        float wx = __fadd_rn(x, __fmul_rn(__fmul_rn(s, f.x), FLOW_SCALE));

        // jnp.round == round half to even == rintf
        float ry = rintf(wy);
        float rx = rintf(wx);

        if (!(ry >= 0.0f && ry < (float)HH && rx >= 0.0f && rx < (float)WW))
            continue;

        int fw = (int)ry * WW + (int)rx;
        int c  = (p > 0.0f) ? 0 : 1;

        // hash dedup: direct CAS (slots go 0 -> tag exactly once)
        uint32_t key = ((uint32_t)c << 30) | ((uint32_t)src << 15) | (uint32_t)fw;
        uint32_t tag = key + 1u;
        uint32_t h   = (key * 2654435761u) >> (32 - TBITS);
        uint32_t* tbl = g_hash + ((size_t)b << TBITS);

        unsigned long long inc = 1ull;           // event count
        while (true) {
            uint32_t old = atomicCAS(&tbl[h], 0u, tag);
            if (old == 0u) { inc = 0x100000001ull; break; }  // first occurrence
            if (old == tag) break;                           // duplicate
            h = (h + 1u) & TMASK;                            // probe next
        }

        size_t chan = (size_t)b * 2 + c;
        atomicAdd(&g_acc[chan * HWSZ + fw], inc);
    }
}

// ---------------------------------------------------------------------------
// Final: out = contrib>0 ? cnt/contrib : 0   (writes every element)
// ---------------------------------------------------------------------------
__global__ void div_kernel(float* __restrict__ out, int n) {
    int i = blockIdx.x * blockDim.x + threadIdx.x;
    if (i >= n) return;
    unsigned long long v = g_acc[i];
    uint32_t cnt = (uint32_t)v;
    uint32_t ctb = (uint32_t)(v >> 32);
    out[i] = (ctb > 0u) ? ((float)cnt / (float)ctb) : 0.0f;
}

extern "C" void kernel_launch(void* const* d_in, const int* in_sizes, int n_in,
                              void* d_out, int out_size) {
    const float*  flow   = (const float*)d_in[0];   // (B, 2, H, W)
    const float4* events = (const float4*)d_in[1];  // (B, N, 4)
    float* out = (float*)d_out;                     // (B, 2, H, W)

    int B = in_sizes[0] / (2 * HWSZ);
    if (B > BMAX) B = BMAX;
    int N = in_sizes[1] / (4 * B);
    int total = B * N;

    prep_kernel<<<4096, 256>>>(flow, B);

    int threads = 256;
    int nthreads = (total + 1) / 2;
    int blocks   = (nthreads + threads - 1) / threads;
    event_kernel<<<blocks, threads>>>(events, N, total);

    int dn = B * 2 * HWSZ;
    div_kernel<<<(dn + 255) / 256, 256>>>(out, dn);
}